// round 2
// baseline (speedup 1.0000x reference)
#include <cuda_runtime.h>
#include <math.h>

// ---------------------------------------------------------------------------
// Fixed scattering network: 2D Morlet scattering (J=4, L=4, N=128, B=64) + MLP
// Strategy: all FFTs are in-smem radix-2, DIF forward (natural->bitrev) and
// DIT inverse (bitrev->natural). PSI precomputed in bit-reversed 2D order so
// spectral multiplies are plain elementwise products. No permutation passes.
// ---------------------------------------------------------------------------

#define NB 64      // batch
#define NN 128     // image size
#define NPIX (NN*NN)
#define PITCH 129  // float2 pitch (odd -> conflict-free strided LDS.64)
#define NTHREADS 512

// ---- scratch (device globals: allocation-free rule) ----
__device__ float2 g_Ihat[NB * NPIX];            // 8 MB, bitrev both dims
__device__ float2 g_U1hat[NB * 3 * 4 * NPIX];   // 96 MB, j1 in {0,1,2}
__device__ float  g_psi[16 * NPIX];             // 1 MB, bitrev both dims
__device__ float  g_s0[NB];
__device__ float  g_s1p[NB * 4 * 4];            // per (b,j,l) spatial sums
__device__ float  g_s2p[NB * 6 * 16];           // per (b,pair,l1*4+l2)

__constant__ int c_j1[6] = {0,0,0,1,1,2};
__constant__ int c_j2[6] = {1,2,3,2,3,3};

static __device__ __forceinline__ float2 cmul(float2 a, float2 b) {
    return make_float2(a.x*b.x - a.y*b.y, a.x*b.y + a.y*b.x);
}
static __device__ __forceinline__ int brev7(int x) {
    return (int)(__brev((unsigned)x) >> 25);
}

// ---------------------------------------------------------------------------
// smem layout helpers
// ---------------------------------------------------------------------------
struct Smem {
    float2* tile;  // [128][PITCH]
    float2* tw;    // [64] W_128^k = exp(-i pi k / 64)
    float*  rbuf;  // [16] warp partials
};
static __device__ __forceinline__ Smem get_smem() {
    extern __shared__ char sm[];
    Smem s;
    s.tile = (float2*)sm;
    s.tw   = s.tile + PITCH * NN;
    s.rbuf = (float*)(s.tw + 64);
    return s;
}

static __device__ __forceinline__ void init_tw(float2* tw) {
    for (int k = threadIdx.x; k < 64; k += blockDim.x) {
        float s, c;
        sincospif((float)k / 64.0f, &s, &c);
        tw[k] = make_float2(c, -s);     // exp(-2*pi*i*k/128)
    }
}

// fixed-order deterministic block reduction (512 threads = 16 warps)
static __device__ __forceinline__ float block_reduce(float v, float* rbuf) {
    #pragma unroll
    for (int o = 16; o > 0; o >>= 1) v += __shfl_down_sync(0xffffffffu, v, o);
    if ((threadIdx.x & 31) == 0) rbuf[threadIdx.x >> 5] = v;
    __syncthreads();
    float s = 0.f;
    if (threadIdx.x == 0) {
        #pragma unroll
        for (int i = 0; i < 16; ++i) s += rbuf[i];
        rbuf[0] = s;
    }
    __syncthreads();
    s = rbuf[0];
    __syncthreads();
    return s;
}

// ---------------------------------------------------------------------------
// 128-pt FFT over one axis of the 128x128 tile, 128 transforms in parallel.
// ROWDIR=true : transform along 2nd index (per-row FFT).    addr = t*PITCH + e
// ROWDIR=false: transform along 1st index (per-column FFT). addr = e*PITCH + t
// Forward: DIF, natural in -> bit-reversed out.
// Inverse: DIT, bit-reversed in -> natural out (conjugate twiddles, no scale).
// ---------------------------------------------------------------------------
template<bool ROWDIR>
static __device__ __forceinline__ int taddr(int e, int t) {
    return ROWDIR ? (t * PITCH + e) : (e * PITCH + t);
}

template<bool ROWDIR, bool INV>
static __device__ void fft_axis(float2* tile, const float2* tw) {
    if (!INV) {
        #pragma unroll
        for (int ls = 7; ls >= 1; --ls) {
            const int half = 1 << (ls - 1);
            const int tshift = 7 - ls;
            #pragma unroll 4
            for (int q = threadIdx.x; q < 8192; q += NTHREADS) {
                int t = q >> 6, k = q & 63;
                int off = k & (half - 1);
                int i0 = 2 * k - off, i1 = i0 + half;
                int A0 = taddr<ROWDIR>(i0, t), A1 = taddr<ROWDIR>(i1, t);
                float2 a = tile[A0], b = tile[A1];
                float2 w = tw[off << tshift];
                tile[A0] = make_float2(a.x + b.x, a.y + b.y);
                float2 d = make_float2(a.x - b.x, a.y - b.y);
                tile[A1] = cmul(d, w);
            }
            __syncthreads();
        }
    } else {
        #pragma unroll
        for (int ls = 1; ls <= 7; ++ls) {
            const int half = 1 << (ls - 1);
            const int tshift = 7 - ls;
            #pragma unroll 4
            for (int q = threadIdx.x; q < 8192; q += NTHREADS) {
                int t = q >> 6, k = q & 63;
                int off = k & (half - 1);
                int i0 = 2 * k - off, i1 = i0 + half;
                int A0 = taddr<ROWDIR>(i0, t), A1 = taddr<ROWDIR>(i1, t);
                float2 a = tile[A0], b = tile[A1];
                float2 w = tw[off << tshift];
                w.y = -w.y;                       // conjugate
                float2 tt = cmul(b, w);
                tile[A0] = make_float2(a.x + tt.x, a.y + tt.y);
                tile[A1] = make_float2(a.x - tt.x, a.y - tt.y);
            }
            __syncthreads();
        }
    }
}

static __device__ __forceinline__ void fft2_fwd(float2* tile, const float2* tw) {
    fft_axis<true,  false>(tile, tw);
    fft_axis<false, false>(tile, tw);
}
static __device__ __forceinline__ void ifft2(float2* tile, const float2* tw) {
    fft_axis<true,  true>(tile, tw);
    fft_axis<false, true>(tile, tw);
}

// ---------------------------------------------------------------------------
// K0: build PSI in bit-reversed 2D order.  grid = 16 (j,l), 256 threads
// ---------------------------------------------------------------------------
static __device__ __forceinline__ float freqval(int i) {
    return (float)((i < 64) ? i : i - 128) * (6.283185307179586476925287e0f / 128.0f);
}

__global__ void k_psi() {
    int j = blockIdx.x >> 2, l = blockIdx.x & 3;
    float k0  = 2.356194490192345f / (float)(1 << j);   // 3*pi/4 / 2^j
    float sg  = 0.8f * (float)(1 << j);
    float s2  = sg * sg;
    float th  = 0.7853981633974483f * (float)l;         // pi*l/4
    float k0x = k0 * cosf(th), k0y = k0 * sinf(th);
    float beta = expf(-0.5f * s2 * k0 * k0);
    float* dst = g_psi + (j * 4 + l) * NPIX;
    for (int e = threadIdx.x; e < NPIX; e += blockDim.x) {
        int r = e >> 7, c = e & 127;
        float kx = freqval(brev7(r));
        float ky = freqval(brev7(c));
        float dx = kx - k0x, dy = ky - k0y;
        float g1 = expf(-0.5f * s2 * (dx * dx + dy * dy));
        float g0 = expf(-0.5f * s2 * (kx * kx + ky * ky));
        dst[e] = g1 - beta * g0;
    }
}

// ---------------------------------------------------------------------------
// K1: I_hat = fft2(image), plus s0.  grid = 64 (one image/block)
// ---------------------------------------------------------------------------
__global__ __launch_bounds__(NTHREADS)
void k_fft_image(const float* __restrict__ img) {
    Smem s = get_smem();
    int b = blockIdx.x;
    init_tw(s.tw);
    float lsum = 0.f;
    const float* src = img + (size_t)b * NPIX;
    for (int e = threadIdx.x; e < NPIX; e += NTHREADS) {
        float v = src[e];
        lsum += v;
        s.tile[(e >> 7) * PITCH + (e & 127)] = make_float2(v, 0.f);
    }
    __syncthreads();
    float tot = block_reduce(lsum, s.rbuf);
    if (threadIdx.x == 0) g_s0[b] = tot * (1.f / 16384.f);
    fft2_fwd(s.tile, s.tw);
    float2* dst = g_Ihat + (size_t)b * NPIX;
    for (int e = threadIdx.x; e < NPIX; e += NTHREADS)
        dst[e] = s.tile[(e >> 7) * PITCH + (e & 127)];
}

// ---------------------------------------------------------------------------
// K2: u1 = |ifft2(I_hat*PSI_{j,l})|; s1 partial; u1_hat = fft2(u1) (j<3).
// grid = 1024 = B*J*L
// ---------------------------------------------------------------------------
__global__ __launch_bounds__(NTHREADS)
void k_first() {
    Smem s = get_smem();
    int idx = blockIdx.x;
    int b = idx >> 4, j = (idx >> 2) & 3, l = idx & 3;
    init_tw(s.tw);
    const float2* ih = g_Ihat + (size_t)b * NPIX;
    const float*  ps = g_psi + (j * 4 + l) * NPIX;
    for (int e = threadIdx.x; e < NPIX; e += NTHREADS) {
        float2 v = ih[e];
        float p = ps[e];
        s.tile[(e >> 7) * PITCH + (e & 127)] = make_float2(v.x * p, v.y * p);
    }
    __syncthreads();
    ifft2(s.tile, s.tw);
    float lsum = 0.f;
    for (int e = threadIdx.x; e < NPIX; e += NTHREADS) {
        int a = (e >> 7) * PITCH + (e & 127);
        float2 z = s.tile[a];
        float u = sqrtf(z.x * z.x + z.y * z.y) * (1.f / 16384.f);
        lsum += u;
        s.tile[a] = make_float2(u, 0.f);
    }
    __syncthreads();
    float tot = block_reduce(lsum, s.rbuf);
    if (threadIdx.x == 0) g_s1p[(b * 4 + j) * 4 + l] = tot;
    if (j < 3) {
        fft2_fwd(s.tile, s.tw);
        float2* dst = g_U1hat + ((size_t)(b * 3 + j) * 4 + l) * NPIX;
        for (int e = threadIdx.x; e < NPIX; e += NTHREADS)
            dst[e] = s.tile[(e >> 7) * PITCH + (e & 127)];
    }
}

// ---------------------------------------------------------------------------
// K3: s2 partial = sum |ifft2(u1_hat_{j1,l1} * PSI_{j2,l2})|.
// grid = 6144 = B * 6 pairs * 16 (l1,l2)
// ---------------------------------------------------------------------------
__global__ __launch_bounds__(NTHREADS)
void k_second() {
    Smem s = get_smem();
    int idx = blockIdx.x;
    int b = idx / 96;
    int r = idx - b * 96;
    int p = r >> 4, l1 = (r >> 2) & 3, l2 = r & 3;
    int j1 = c_j1[p], j2 = c_j2[p];
    init_tw(s.tw);
    const float2* uh = g_U1hat + ((size_t)(b * 3 + j1) * 4 + l1) * NPIX;
    const float*  ps = g_psi + (j2 * 4 + l2) * NPIX;
    for (int e = threadIdx.x; e < NPIX; e += NTHREADS) {
        float2 v = uh[e];
        float q = ps[e];
        s.tile[(e >> 7) * PITCH + (e & 127)] = make_float2(v.x * q, v.y * q);
    }
    __syncthreads();
    ifft2(s.tile, s.tw);
    float lsum = 0.f;
    for (int e = threadIdx.x; e < NPIX; e += NTHREADS) {
        float2 z = s.tile[(e >> 7) * PITCH + (e & 127)];
        lsum += sqrtf(z.x * z.x + z.y * z.y);
    }
    __syncthreads();
    float tot = block_reduce(lsum, s.rbuf);
    if (threadIdx.x == 0) g_s2p[(b * 6 + p) * 16 + (l1 * 4 + l2)] = tot * (1.f / 16384.f);
}

// ---------------------------------------------------------------------------
// K4: finalize coefficients + MLP.  1 block, 64 threads (one per batch elem)
// ---------------------------------------------------------------------------
__global__ void k_final(const float* __restrict__ fc1w, const float* __restrict__ fc1b,
                        const float* __restrict__ fc2w, const float* __restrict__ fc2b,
                        float* __restrict__ out) {
    int b = threadIdx.x;
    if (b >= NB) return;
    float coeffs[11];
    coeffs[0] = g_s0[b];
    #pragma unroll
    for (int j = 0; j < 4; ++j) {
        float s = 0.f;
        #pragma unroll
        for (int l = 0; l < 4; ++l) s += g_s1p[(b * 4 + j) * 4 + l];
        coeffs[1 + j] = s * (1.f / 65536.f);   // / (L * N * N)
    }
    #pragma unroll
    for (int p = 0; p < 6; ++p) {
        float s = 0.f;
        #pragma unroll
        for (int i = 0; i < 16; ++i) s += g_s2p[(b * 6 + p) * 16 + i];
        coeffs[5 + p] = s * (1.f / (16.f * 16384.f));  // / (L1*L2*N*N)
    }
    float h[4];
    #pragma unroll
    for (int i = 0; i < 4; ++i) {
        float a = fc1b[i];
        #pragma unroll
        for (int k = 0; k < 11; ++k) a += coeffs[k] * fc1w[i * 11 + k];
        h[i] = fmaxf(a, 0.f);
    }
    #pragma unroll
    for (int o = 0; o < 10; ++o) {
        float a = fc2b[o];
        #pragma unroll
        for (int i = 0; i < 4; ++i) a += h[i] * fc2w[o * 4 + i];
        out[b * 10 + o] = 1.f / (1.f + expf(-a));
    }
}

// ---------------------------------------------------------------------------
extern "C" void kernel_launch(void* const* d_in, const int* in_sizes, int n_in,
                              void* d_out, int out_size) {
    (void)in_sizes; (void)n_in; (void)out_size;
    const float* img  = (const float*)d_in[0];
    const float* fc1w = (const float*)d_in[1];
    const float* fc1b = (const float*)d_in[2];
    const float* fc2w = (const float*)d_in[3];
    const float* fc2b = (const float*)d_in[4];
    float* out = (float*)d_out;

    const int smem_sz = PITCH * NN * (int)sizeof(float2)
                      + 64 * (int)sizeof(float2) + 16 * (int)sizeof(float);
    cudaFuncSetAttribute(k_fft_image, cudaFuncAttributeMaxDynamicSharedMemorySize, smem_sz);
    cudaFuncSetAttribute(k_first,     cudaFuncAttributeMaxDynamicSharedMemorySize, smem_sz);
    cudaFuncSetAttribute(k_second,    cudaFuncAttributeMaxDynamicSharedMemorySize, smem_sz);

    k_psi<<<16, 256>>>();
    k_fft_image<<<NB, NTHREADS, smem_sz>>>(img);
    k_first<<<NB * 16, NTHREADS, smem_sz>>>();
    k_second<<<NB * 96, NTHREADS, smem_sz>>>();
    k_final<<<1, 64>>>(fc1w, fc1b, fc2w, fc2b, out);
}

// round 3
// speedup vs baseline: 3.5162x; 3.5162x over previous
#include <cuda_runtime.h>
#include <math.h>

// ---------------------------------------------------------------------------
// Fixed scattering network: 2D Morlet scattering (J=4, L=4, N=128, B=64) + MLP
// FFTs: in-smem Cooley-Tukey, DIF forward (natural->bitrev), DIT inverse
// (bitrev->natural). PSI precomputed in bit-reversed 2D order.
// R2 change: radix-8 + radix-16 fused stages (2 smem round trips per axis
// instead of 7), epilogue (|.| + reduction) fused into final inverse pass.
// ---------------------------------------------------------------------------

#define NB 64      // batch
#define NN 128     // image size
#define NPIX (NN*NN)
#define PITCH 129  // float2 pitch (odd -> conflict-free strided LDS.64)
#define NTHREADS 512

// ---- scratch (device globals: allocation-free rule) ----
__device__ float2 g_Ihat[NB * NPIX];            // 8 MB, bitrev both dims
__device__ float2 g_U1hat[NB * 3 * 4 * NPIX];   // 96 MB, j1 in {0,1,2}
__device__ float  g_psi[16 * NPIX];             // 1 MB, bitrev both dims
__device__ float  g_s0[NB];
__device__ float  g_s1p[NB * 4 * 4];            // per (b,j,l) spatial sums
__device__ float  g_s2p[NB * 6 * 16];           // per (b,pair,l1*4+l2)

__constant__ int c_j1[6] = {0,0,0,1,1,2};
__constant__ int c_j2[6] = {1,2,3,2,3,3};

static __device__ __forceinline__ float2 cadd(float2 a, float2 b){ return make_float2(a.x+b.x, a.y+b.y); }
static __device__ __forceinline__ float2 csub(float2 a, float2 b){ return make_float2(a.x-b.x, a.y-b.y); }
static __device__ __forceinline__ float2 cmul(float2 a, float2 b){ return make_float2(a.x*b.x-a.y*b.y, a.x*b.y+a.y*b.x); }
static __device__ __forceinline__ float2 cconj(float2 a){ return make_float2(a.x, -a.y); }
static __device__ __forceinline__ float2 mul_negi(float2 a){ return make_float2(a.y, -a.x); }   // a * (-i)
static __device__ __forceinline__ float2 mul_i(float2 a){ return make_float2(-a.y, a.x); }      // a * (+i)
static __device__ __forceinline__ int brev7(int x){ return (int)(__brev((unsigned)x) >> 25); }

// ---------------------------------------------------------------------------
// smem layout
// ---------------------------------------------------------------------------
struct Smem {
    float2* tile;  // [128][PITCH]
    float2* tw;    // [64] W_128^k = exp(-2 pi i k / 128)
    float*  rbuf;  // [16] warp partials
};
static __device__ __forceinline__ Smem get_smem() {
    extern __shared__ char sm[];
    Smem s;
    s.tile = (float2*)sm;
    s.tw   = s.tile + PITCH * NN;
    s.rbuf = (float*)(s.tw + 64);
    return s;
}

static __device__ __forceinline__ void init_tw(float2* tw) {
    for (int k = threadIdx.x; k < 64; k += blockDim.x) {
        float s, c;
        sincospif((float)k / 64.0f, &s, &c);
        tw[k] = make_float2(c, -s);
    }
}

// fixed-order deterministic block reduction (512 threads = 16 warps)
static __device__ __forceinline__ float block_reduce(float v, float* rbuf) {
    #pragma unroll
    for (int o = 16; o > 0; o >>= 1) v += __shfl_down_sync(0xffffffffu, v, o);
    if ((threadIdx.x & 31) == 0) rbuf[threadIdx.x >> 5] = v;
    __syncthreads();
    float s = 0.f;
    if (threadIdx.x == 0) {
        #pragma unroll
        for (int i = 0; i < 16; ++i) s += rbuf[i];
        rbuf[0] = s;
    }
    __syncthreads();
    s = rbuf[0];
    __syncthreads();
    return s;
}

// ---------------------------------------------------------------------------
// Radix-8 pass: DIF stage halves {64,32,16} (fwd) / DIT halves {16,32,64} (inv)
// m = 16: elements e_j = off + 16*j, off in [0,16), per transform t.
// Lane map: t = q & 127 (varies along lanes -> conflict-free LDS.64).
// ---------------------------------------------------------------------------
#define C_SQH 0.70710678118654752440f

template<bool ROW>
static __device__ void pass_r8_fwd(float2* tile, const float2* tw) {
    #pragma unroll
    for (int k = 0; k < 4; ++k) {
        int q = threadIdx.x + k * NTHREADS;
        int t = q & 127, off = q >> 7;
        int base = ROW ? t * PITCH + off : off * PITCH + t;
        int str  = ROW ? 16 : 16 * PITCH;
        float2 x[8];
        #pragma unroll
        for (int j = 0; j < 8; ++j) x[j] = tile[base + j * str];
        float2 w1 = tw[off], w2 = tw[2*off], w4 = tw[4*off];
        float2 w1c1 = cmul(w1, make_float2(C_SQH, -C_SQH));
        float2 w1c2 = mul_negi(w1);
        float2 w1c3 = cmul(w1, make_float2(-C_SQH, -C_SQH));
        float2 a, b;
        // stage half=4m: pairs (j, j+4), tw = w1 * W^{16 j}
        a=x[0]; b=x[4]; x[0]=cadd(a,b); x[4]=cmul(csub(a,b), w1);
        a=x[1]; b=x[5]; x[1]=cadd(a,b); x[5]=cmul(csub(a,b), w1c1);
        a=x[2]; b=x[6]; x[2]=cadd(a,b); x[6]=cmul(csub(a,b), w1c2);
        a=x[3]; b=x[7]; x[3]=cadd(a,b); x[7]=cmul(csub(a,b), w1c3);
        // stage half=2m: pairs (0,2),(1,3),(4,6),(5,7), tw = w2 * (-i)^{pair}
        float2 w2n = mul_negi(w2);
        a=x[0]; b=x[2]; x[0]=cadd(a,b); x[2]=cmul(csub(a,b), w2);
        a=x[1]; b=x[3]; x[1]=cadd(a,b); x[3]=cmul(csub(a,b), w2n);
        a=x[4]; b=x[6]; x[4]=cadd(a,b); x[6]=cmul(csub(a,b), w2);
        a=x[5]; b=x[7]; x[5]=cadd(a,b); x[7]=cmul(csub(a,b), w2n);
        // stage half=m: pairs (2p, 2p+1), tw = w4
        #pragma unroll
        for (int p = 0; p < 4; ++p) {
            a=x[2*p]; b=x[2*p+1];
            x[2*p]=cadd(a,b); x[2*p+1]=cmul(csub(a,b), w4);
        }
        #pragma unroll
        for (int j = 0; j < 8; ++j) tile[base + j * str] = x[j];
    }
}

// EPI: 0 = store complex result, 1 = accumulate |y| (no store), 2 = store (|y|*scale, 0) and accumulate
template<bool ROW, int EPI>
static __device__ float pass_r8_inv(float2* tile, const float2* tw, float scale) {
    float acc = 0.f;
    #pragma unroll
    for (int k = 0; k < 4; ++k) {
        int q = threadIdx.x + k * NTHREADS;
        int t = q & 127, off = q >> 7;
        int base = ROW ? t * PITCH + off : off * PITCH + t;
        int str  = ROW ? 16 : 16 * PITCH;
        float2 x[8];
        #pragma unroll
        for (int j = 0; j < 8; ++j) x[j] = tile[base + j * str];
        float2 w1c = cconj(tw[off]), w2c = cconj(tw[2*off]), w4c = cconj(tw[4*off]);
        float2 a, bw;
        // stage half=m (DIT): pairs (2p,2p+1), tw = conj(w4)
        #pragma unroll
        for (int p = 0; p < 4; ++p) {
            a=x[2*p]; bw=cmul(x[2*p+1], w4c);
            x[2*p]=cadd(a,bw); x[2*p+1]=csub(a,bw);
        }
        // stage half=2m: (0,2)/(4,6) conj(w2); (1,3)/(5,7) conj(w2*(-i)) = conj(w2)*i
        float2 w2ci = mul_i(w2c);
        a=x[0]; bw=cmul(x[2], w2c ); x[0]=cadd(a,bw); x[2]=csub(a,bw);
        a=x[1]; bw=cmul(x[3], w2ci); x[1]=cadd(a,bw); x[3]=csub(a,bw);
        a=x[4]; bw=cmul(x[6], w2c ); x[4]=cadd(a,bw); x[6]=csub(a,bw);
        a=x[5]; bw=cmul(x[7], w2ci); x[5]=cadd(a,bw); x[7]=csub(a,bw);
        // stage half=4m: pairs (j,j+4), tw = conj(w1 * W^{16 j})
        float2 u0 = w1c;
        float2 u1 = cmul(w1c, make_float2(C_SQH, C_SQH));
        float2 u2 = mul_i(w1c);
        float2 u3 = cmul(w1c, make_float2(-C_SQH, C_SQH));
        a=x[0]; bw=cmul(x[4], u0); x[0]=cadd(a,bw); x[4]=csub(a,bw);
        a=x[1]; bw=cmul(x[5], u1); x[1]=cadd(a,bw); x[5]=csub(a,bw);
        a=x[2]; bw=cmul(x[6], u2); x[2]=cadd(a,bw); x[6]=csub(a,bw);
        a=x[3]; bw=cmul(x[7], u3); x[3]=cadd(a,bw); x[7]=csub(a,bw);
        if (EPI == 0) {
            #pragma unroll
            for (int j = 0; j < 8; ++j) tile[base + j * str] = x[j];
        } else {
            #pragma unroll
            for (int j = 0; j < 8; ++j) {
                float m = sqrtf(x[j].x * x[j].x + x[j].y * x[j].y);
                if (EPI == 2) {
                    m *= scale;
                    tile[base + j * str] = make_float2(m, 0.f);
                }
                acc += m;
            }
        }
    }
    return acc;
}

// ---------------------------------------------------------------------------
// Radix-16 pass: DIF stage halves {8,4,2,1} (fwd) / DIT halves {1,2,4,8} (inv)
// m = 1: elements e_j = 16*g + j. All twiddles compile-time constants.
// Lane map: t = q & 127.
// ---------------------------------------------------------------------------
#define C_S1 0.92387953251128675613f  // cos(pi/8)
#define C_S3 0.38268343236508977173f  // sin(pi/8)

template<bool ROW, bool INV>
static __device__ void pass_r16(float2* tile) {
    #pragma unroll
    for (int k = 0; k < 2; ++k) {
        int q = threadIdx.x + k * NTHREADS;
        int t = q & 127, g = q >> 7;
        int base = ROW ? t * PITCH + 16 * g : (16 * g) * PITCH + t;
        int str  = ROW ? 1 : PITCH;
        float2 x[16];
        #pragma unroll
        for (int j = 0; j < 16; ++j) x[j] = tile[base + j * str];
        float2 a, b, bw;
        if (!INV) {
            const float2 W8[8] = {{1.f,0.f},{C_S1,-C_S3},{C_SQH,-C_SQH},{C_S3,-C_S1},
                                  {0.f,-1.f},{-C_S3,-C_S1},{-C_SQH,-C_SQH},{-C_S1,-C_S3}};
            const float2 W16[4] = {{1.f,0.f},{C_SQH,-C_SQH},{0.f,-1.f},{-C_SQH,-C_SQH}};
            #pragma unroll
            for (int j = 0; j < 8; ++j) {
                a=x[j]; b=x[j+8]; x[j]=cadd(a,b); x[j+8]=cmul(csub(a,b), W8[j]);
            }
            #pragma unroll
            for (int h = 0; h < 16; h += 8)
                #pragma unroll
                for (int j = 0; j < 4; ++j) {
                    a=x[h+j]; b=x[h+j+4]; x[h+j]=cadd(a,b); x[h+j+4]=cmul(csub(a,b), W16[j]);
                }
            #pragma unroll
            for (int h = 0; h < 16; h += 4) {
                a=x[h];   b=x[h+2]; x[h]  =cadd(a,b); x[h+2]=csub(a,b);
                a=x[h+1]; b=x[h+3]; x[h+1]=cadd(a,b); x[h+3]=mul_negi(csub(a,b));
            }
            #pragma unroll
            for (int h = 0; h < 16; h += 2) {
                a=x[h]; b=x[h+1]; x[h]=cadd(a,b); x[h+1]=csub(a,b);
            }
        } else {
            const float2 W16c[4] = {{1.f,0.f},{C_SQH,C_SQH},{0.f,1.f},{-C_SQH,C_SQH}};
            const float2 W8c[8]  = {{1.f,0.f},{C_S1,C_S3},{C_SQH,C_SQH},{C_S3,C_S1},
                                    {0.f,1.f},{-C_S3,C_S1},{-C_SQH,C_SQH},{-C_S1,C_S3}};
            #pragma unroll
            for (int h = 0; h < 16; h += 2) {
                a=x[h]; b=x[h+1]; x[h]=cadd(a,b); x[h+1]=csub(a,b);
            }
            #pragma unroll
            for (int h = 0; h < 16; h += 4) {
                a=x[h];   b=x[h+2];        x[h]  =cadd(a,b);  x[h+2]=csub(a,b);
                a=x[h+1]; bw=mul_i(x[h+3]); x[h+1]=cadd(a,bw); x[h+3]=csub(a,bw);
            }
            #pragma unroll
            for (int h = 0; h < 16; h += 8)
                #pragma unroll
                for (int j = 0; j < 4; ++j) {
                    a=x[h+j]; bw=cmul(x[h+j+4], W16c[j]);
                    x[h+j]=cadd(a,bw); x[h+j+4]=csub(a,bw);
                }
            #pragma unroll
            for (int j = 0; j < 8; ++j) {
                a=x[j]; bw=cmul(x[j+8], W8c[j]);
                x[j]=cadd(a,bw); x[j+8]=csub(a,bw);
            }
        }
        #pragma unroll
        for (int j = 0; j < 16; ++j) tile[base + j * str] = x[j];
    }
}

// Full 2D transforms (per axis: r8 then r16 for DIF; r16 then r8 for DIT)
static __device__ __forceinline__ void fft2_fwd(float2* tile, const float2* tw) {
    pass_r8_fwd<true >(tile, tw); __syncthreads();
    pass_r16<true,  false>(tile); __syncthreads();
    pass_r8_fwd<false>(tile, tw); __syncthreads();
    pass_r16<false, false>(tile); __syncthreads();
}

// ---------------------------------------------------------------------------
// K0: build PSI in bit-reversed 2D order.  grid = 16 (j,l), 256 threads
// ---------------------------------------------------------------------------
static __device__ __forceinline__ float freqval(int i) {
    return (float)((i < 64) ? i : i - 128) * (6.283185307179586476925287e0f / 128.0f);
}

__global__ void k_psi() {
    int j = blockIdx.x >> 2, l = blockIdx.x & 3;
    float k0  = 2.356194490192345f / (float)(1 << j);
    float sg  = 0.8f * (float)(1 << j);
    float s2  = sg * sg;
    float th  = 0.7853981633974483f * (float)l;
    float k0x = k0 * cosf(th), k0y = k0 * sinf(th);
    float beta = expf(-0.5f * s2 * k0 * k0);
    float* dst = g_psi + (j * 4 + l) * NPIX;
    for (int e = threadIdx.x; e < NPIX; e += blockDim.x) {
        int r = e >> 7, c = e & 127;
        float kx = freqval(brev7(r));
        float ky = freqval(brev7(c));
        float dx = kx - k0x, dy = ky - k0y;
        float g1 = expf(-0.5f * s2 * (dx * dx + dy * dy));
        float g0 = expf(-0.5f * s2 * (kx * kx + ky * ky));
        dst[e] = g1 - beta * g0;
    }
}

// ---------------------------------------------------------------------------
// K1: I_hat = fft2(image), plus s0.  grid = 64
// ---------------------------------------------------------------------------
__global__ __launch_bounds__(NTHREADS, 1)
void k_fft_image(const float* __restrict__ img) {
    Smem s = get_smem();
    int b = blockIdx.x;
    init_tw(s.tw);
    float lsum = 0.f;
    const float* src = img + (size_t)b * NPIX;
    for (int e = threadIdx.x; e < NPIX; e += NTHREADS) {
        float v = src[e];
        lsum += v;
        s.tile[(e >> 7) * PITCH + (e & 127)] = make_float2(v, 0.f);
    }
    __syncthreads();
    float tot = block_reduce(lsum, s.rbuf);
    if (threadIdx.x == 0) g_s0[b] = tot * (1.f / 16384.f);
    fft2_fwd(s.tile, s.tw);
    float2* dst = g_Ihat + (size_t)b * NPIX;
    for (int e = threadIdx.x; e < NPIX; e += NTHREADS)
        dst[e] = s.tile[(e >> 7) * PITCH + (e & 127)];
}

// ---------------------------------------------------------------------------
// K2: u1 = |ifft2(I_hat*PSI_{j,l})|; s1 partial; u1_hat = fft2(u1) (j<3).
// grid = 1024
// ---------------------------------------------------------------------------
__global__ __launch_bounds__(NTHREADS, 1)
void k_first() {
    Smem s = get_smem();
    int idx = blockIdx.x;
    int b = idx >> 4, j = (idx >> 2) & 3, l = idx & 3;
    init_tw(s.tw);
    const float2* ih = g_Ihat + (size_t)b * NPIX;
    const float*  ps = g_psi + (j * 4 + l) * NPIX;
    for (int e = threadIdx.x; e < NPIX; e += NTHREADS) {
        float2 v = ih[e];
        float p = ps[e];
        s.tile[(e >> 7) * PITCH + (e & 127)] = make_float2(v.x * p, v.y * p);
    }
    __syncthreads();
    // inverse 2D, final pass fused with |.|*scale store + accumulation
    pass_r16<true,  true>(s.tile); __syncthreads();
    pass_r8_inv<true, 0>(s.tile, s.tw, 0.f); __syncthreads();
    pass_r16<false, true>(s.tile); __syncthreads();
    float lsum = pass_r8_inv<false, 2>(s.tile, s.tw, 1.f / 16384.f);
    float tot = block_reduce(lsum, s.rbuf);   // syncs inside cover tile writes
    if (threadIdx.x == 0) g_s1p[(b * 4 + j) * 4 + l] = tot;
    if (j < 3) {
        fft2_fwd(s.tile, s.tw);
        float2* dst = g_U1hat + ((size_t)(b * 3 + j) * 4 + l) * NPIX;
        for (int e = threadIdx.x; e < NPIX; e += NTHREADS)
            dst[e] = s.tile[(e >> 7) * PITCH + (e & 127)];
    }
}

// ---------------------------------------------------------------------------
// K3: s2 partial = sum |ifft2(u1_hat_{j1,l1} * PSI_{j2,l2})|.  grid = 6144
// ---------------------------------------------------------------------------
__global__ __launch_bounds__(NTHREADS, 1)
void k_second() {
    Smem s = get_smem();
    int idx = blockIdx.x;
    int b = idx / 96;
    int r = idx - b * 96;
    int p = r >> 4, l1 = (r >> 2) & 3, l2 = r & 3;
    int j1 = c_j1[p], j2 = c_j2[p];
    init_tw(s.tw);
    const float2* uh = g_U1hat + ((size_t)(b * 3 + j1) * 4 + l1) * NPIX;
    const float*  ps = g_psi + (j2 * 4 + l2) * NPIX;
    for (int e = threadIdx.x; e < NPIX; e += NTHREADS) {
        float2 v = uh[e];
        float q = ps[e];
        s.tile[(e >> 7) * PITCH + (e & 127)] = make_float2(v.x * q, v.y * q);
    }
    __syncthreads();
    pass_r16<true,  true>(s.tile); __syncthreads();
    pass_r8_inv<true, 0>(s.tile, s.tw, 0.f); __syncthreads();
    pass_r16<false, true>(s.tile); __syncthreads();
    float lsum = pass_r8_inv<false, 1>(s.tile, s.tw, 0.f);  // magnitudes from registers
    float tot = block_reduce(lsum, s.rbuf);
    if (threadIdx.x == 0) g_s2p[(b * 6 + p) * 16 + (l1 * 4 + l2)] = tot * (1.f / 16384.f);
}

// ---------------------------------------------------------------------------
// K4: finalize coefficients + MLP.  1 block, 64 threads
// ---------------------------------------------------------------------------
__global__ void k_final(const float* __restrict__ fc1w, const float* __restrict__ fc1b,
                        const float* __restrict__ fc2w, const float* __restrict__ fc2b,
                        float* __restrict__ out) {
    int b = threadIdx.x;
    if (b >= NB) return;
    float coeffs[11];
    coeffs[0] = g_s0[b];
    #pragma unroll
    for (int j = 0; j < 4; ++j) {
        float s = 0.f;
        #pragma unroll
        for (int l = 0; l < 4; ++l) s += g_s1p[(b * 4 + j) * 4 + l];
        coeffs[1 + j] = s * (1.f / 65536.f);
    }
    #pragma unroll
    for (int p = 0; p < 6; ++p) {
        float s = 0.f;
        #pragma unroll
        for (int i = 0; i < 16; ++i) s += g_s2p[(b * 6 + p) * 16 + i];
        coeffs[5 + p] = s * (1.f / (16.f * 16384.f));
    }
    float h[4];
    #pragma unroll
    for (int i = 0; i < 4; ++i) {
        float a = fc1b[i];
        #pragma unroll
        for (int k = 0; k < 11; ++k) a += coeffs[k] * fc1w[i * 11 + k];
        h[i] = fmaxf(a, 0.f);
    }
    #pragma unroll
    for (int o = 0; o < 10; ++o) {
        float a = fc2b[o];
        #pragma unroll
        for (int i = 0; i < 4; ++i) a += h[i] * fc2w[o * 4 + i];
        out[b * 10 + o] = 1.f / (1.f + expf(-a));
    }
}

// ---------------------------------------------------------------------------
extern "C" void kernel_launch(void* const* d_in, const int* in_sizes, int n_in,
                              void* d_out, int out_size) {
    (void)in_sizes; (void)n_in; (void)out_size;
    const float* img  = (const float*)d_in[0];
    const float* fc1w = (const float*)d_in[1];
    const float* fc1b = (const float*)d_in[2];
    const float* fc2w = (const float*)d_in[3];
    const float* fc2b = (const float*)d_in[4];
    float* out = (float*)d_out;

    const int smem_sz = PITCH * NN * (int)sizeof(float2)
                      + 64 * (int)sizeof(float2) + 16 * (int)sizeof(float);
    cudaFuncSetAttribute(k_fft_image, cudaFuncAttributeMaxDynamicSharedMemorySize, smem_sz);
    cudaFuncSetAttribute(k_first,     cudaFuncAttributeMaxDynamicSharedMemorySize, smem_sz);
    cudaFuncSetAttribute(k_second,    cudaFuncAttributeMaxDynamicSharedMemorySize, smem_sz);

    k_psi<<<16, 256>>>();
    k_fft_image<<<NB, NTHREADS, smem_sz>>>(img);
    k_first<<<NB * 16, NTHREADS, smem_sz>>>();
    k_second<<<NB * 96, NTHREADS, smem_sz>>>();
    k_final<<<1, 64>>>(fc1w, fc1b, fc2w, fc2b, out);
}